// round 17
// baseline (speedup 1.0000x reference)
#include <cuda_runtime.h>
#include <cstdint>

// BinCat: idx = sum_j (1 - x[b,i,j]) * 2^(19-j), out[row,:] = cats[idx,:]
// x:    (4096, 16, 20) int32 (0/1)   -> 65536 rows of 80 B (16B-aligned)
// cats: (2^20, 64) float32           -> 256 B rows (256B-aligned)
// out:  (4096, 16, 64) float32
//
// R17 = R16 (tied-best 8.70us) made PERSISTENT (grid-stride over tiles).
//   All structures converge at dur = 22MB / ~2.5TB/s random-256B drain =>
//   pattern-bound. Remaining overhead: wave structure (1024 CTAs = ~7
//   waves) and the cold x-load phase head each new CTA pays.
//   Fix: 512 resident CTAs, each loops over 2 tiles. Across iterations the
//   next tile's x-loads are independent of the current tile's gathers ->
//   scoreboard overlaps the phases (soft pipeline), and wave transitions
//   mostly vanish.
//   Per-tile structure identical to R16: 8 rows/warp, lanes 0..7 compute
//   indices, 2x LDG.256 (evict_last) gather, plain STG.256 stores.

static constexpr int LENGTH        = 20;
static constexpr int DIM           = 64;   // 256 B per row
static constexpr int ROWS_PER_WARP = 8;
static constexpr int WARPS_PER_CTA = 8;    // 256 threads
static constexpr int ROWS_PER_CTA  = ROWS_PER_WARP * WARPS_PER_CTA;  // 64

__device__ __forceinline__ void ldg_el_256(const void* p,
                                           unsigned long long r[4])
{
    asm volatile("ld.global.nc.L2::evict_last.v4.b64 {%0,%1,%2,%3}, [%4];"
                 : "=l"(r[0]), "=l"(r[1]), "=l"(r[2]), "=l"(r[3])
                 : "l"(p));
}

__device__ __forceinline__ void stg_256(void* p,
                                        const unsigned long long r[4])
{
    asm volatile("st.global.v4.b64 [%0], {%1,%2,%3,%4};"
                 :: "l"(p), "l"(r[0]), "l"(r[1]), "l"(r[2]), "l"(r[3])
                 : "memory");
}

__global__ void __launch_bounds__(256)
bincat_gather_kernel(const int* __restrict__ x,
                     const float* __restrict__ cats,
                     float* __restrict__ out,
                     int ntiles, int nrows)
{
    const int warp_in_cta = threadIdx.x >> 5;
    const int lane        = threadIdx.x & 31;
    const int sub         = lane >> 3;   // 0..3: row within group of 4
    const int chunk       = lane & 7;    // 0..7: 32B chunk within 256B row

    for (int tile = blockIdx.x; tile < ntiles; tile += gridDim.x) {
        const int row_base = tile * ROWS_PER_CTA + warp_in_cta * ROWS_PER_WARP;

        // ---- Phase 1: lanes 0..7 compute indices (80 B = 5 x int4) ----
        unsigned idx = 0u;
        {
            const int myrow = row_base + lane;
            if (lane < ROWS_PER_WARP && myrow < nrows) {
                const int4* __restrict__ xr =
                    reinterpret_cast<const int4*>(x + (size_t)myrow * LENGTH);
                const int4 a0 = __ldg(&xr[0]);
                const int4 a1 = __ldg(&xr[1]);
                const int4 a2 = __ldg(&xr[2]);
                const int4 a3 = __ldg(&xr[3]);
                const int4 a4 = __ldg(&xr[4]);
                const int v[LENGTH] = { a0.x, a0.y, a0.z, a0.w,
                                        a1.x, a1.y, a1.z, a1.w,
                                        a2.x, a2.y, a2.z, a2.w,
                                        a3.x, a3.y, a3.z, a3.w,
                                        a4.x, a4.y, a4.z, a4.w };
                #pragma unroll
                for (int j = 0; j < LENGTH; ++j)
                    idx |= (unsigned)(1 - v[j]) << (LENGTH - 1 - j);
            }
        }

        // ---- Phase 2: 256-bit cooperative gather (2 groups of 4 rows) ----
        unsigned long long v0[4], v1[4];
        const int r0 = row_base + sub;
        const int r1 = row_base + 4 + sub;
        {
            const unsigned ridx = __shfl_sync(0xffffffffu, idx, sub);
            const char* src = reinterpret_cast<const char*>(cats)
                            + ((size_t)ridx * 256u) + (size_t)chunk * 32u;
            ldg_el_256(src, v0);
        }
        {
            const unsigned ridx = __shfl_sync(0xffffffffu, idx, 4 + sub);
            const char* src = reinterpret_cast<const char*>(cats)
                            + ((size_t)ridx * 256u) + (size_t)chunk * 32u;
            ldg_el_256(src, v1);
        }

        // ---- stores: plain 256-bit (dirty lines park in L2) ----
        if (r0 < nrows) {
            char* dst = reinterpret_cast<char*>(out)
                      + (size_t)r0 * 256u + (size_t)chunk * 32u;
            stg_256(dst, v0);
        }
        if (r1 < nrows) {
            char* dst = reinterpret_cast<char*>(out)
                      + (size_t)r1 * 256u + (size_t)chunk * 32u;
            stg_256(dst, v1);
        }
        // no barrier: next iteration's x-loads are independent -> overlap
    }
}

extern "C" void kernel_launch(void* const* d_in, const int* in_sizes, int n_in,
                              void* d_out, int out_size)
{
    const int*   x    = (const int*)d_in[0];    // (B, I, 20) int32
    const float* cats = (const float*)d_in[1];  // (2^20, 64) float32
    float*       out  = (float*)d_out;          // (B, I, 64) float32

    const int nrows  = in_sizes[0] / LENGTH;    // 65536
    const int ntiles = (nrows + ROWS_PER_CTA - 1) / ROWS_PER_CTA;  // 1024

    const int threads = 256;
    int blocks = 512;                            // persistent: 2 tiles/CTA
    if (blocks > ntiles) blocks = ntiles;

    bincat_gather_kernel<<<blocks, threads>>>(x, cats, out, ntiles, nrows);
}